// round 16
// baseline (speedup 1.0000x reference)
#include <cuda_runtime.h>
#include <cuda_bf16.h>

#define N       512
#define D       2048
#define LDIM    128
#define PARTS   8
#define SPLITK  4
#define KSPLIT  (D / SPLITK)       // 512
#define KC      32                 // k per pipeline chunk
#define NCH     (KSPLIT / KC)      // 16
#define NTILES  36
#define GRID    148
#define MARGIN  0.3f

#define SM_STRIDE 80                       // bytes per smem row (32 bf16 + 8 pad)
#define TILE_B    (64 * SM_STRIDE)         // 5120
#define STAGE_B   (4 * TILE_B)             // 20480 (Ah, Al, Bh, Bl)
#define LSTRIDE   (LDIM + 4)               // floats per part row
#define GRP_B     16384                    // arena bytes per mine group

// ---------------- device scratch (static allocation only) ----------------
__device__ float          g_sq[N];
__device__ __nv_bfloat16  g_xh[N * D];
__device__ __nv_bfloat16  g_xl[N * D];
__device__ float          g_gram[SPLITK][N * N];
__device__ float          g_gl[N];
__device__ float          g_ll[N];
__device__ int            g_bar0 = 0;
__device__ int            g_bar1 = 0;
__device__ int            g_cnt  = 0;

// symmetric tile list: all (mt, nt) with mt <= nt on the 8x8 grid of 64x64 tiles
__constant__ unsigned char c_mt[NTILES] = {
    0,0,0,0,0,0,0,0, 1,1,1,1,1,1,1, 2,2,2,2,2,2, 3,3,3,3,3, 4,4,4,4, 5,5,5, 6,6, 7};
__constant__ unsigned char c_nt[NTILES] = {
    0,1,2,3,4,5,6,7, 1,2,3,4,5,6,7, 2,3,4,5,6,7, 3,4,5,6,7, 4,5,6,7, 5,6,7, 6,7, 7};

// ---------------- helpers ----------------
__device__ __forceinline__ unsigned s2u(const void* p) {
    unsigned a;
    asm("{ .reg .u64 t; cvta.to.shared.u64 t, %1; cvt.u32.u64 %0, t; }"
        : "=r"(a) : "l"(p));
    return a;
}
__device__ __forceinline__ void cpa16(unsigned saddr, const void* gaddr) {
    asm volatile("cp.async.cg.shared.global [%0], [%1], 16;"
                 :: "r"(saddr), "l"(gaddr) : "memory");
}
__device__ __forceinline__ void ldm4(unsigned* f, unsigned saddr) {
    asm volatile("ldmatrix.sync.aligned.m8n8.x4.shared.b16 {%0,%1,%2,%3}, [%4];"
                 : "=r"(f[0]), "=r"(f[1]), "=r"(f[2]), "=r"(f[3]) : "r"(saddr));
}
__device__ __forceinline__ void mma_bf16(float* d, const unsigned* a,
                                         unsigned b0, unsigned b1) {
    asm volatile(
        "mma.sync.aligned.m16n8k16.row.col.f32.bf16.bf16.f32 "
        "{%0,%1,%2,%3}, {%4,%5,%6,%7}, {%8,%9}, {%0,%1,%2,%3};"
        : "+f"(d[0]), "+f"(d[1]), "+f"(d[2]), "+f"(d[3])
        : "r"(a[0]), "r"(a[1]), "r"(a[2]), "r"(a[3]), "r"(b0), "r"(b1));
}
__device__ __forceinline__ int ld_acq(const int* p) {
    int v;
    asm volatile("ld.acquire.gpu.global.b32 %0, [%1];" : "=r"(v) : "l"(p) : "memory");
    return v;
}
// grid-wide barrier: all GRID CTAs are co-resident (grid == SM count).
__device__ __forceinline__ void grid_bar(int* ctr) {
    __syncthreads();
    if (threadIdx.x == 0) {
        __threadfence();
        atomicAdd(ctr, 1);
        while (ld_acq(ctr) < GRID) { }
    }
    __syncthreads();
}
#define GROUP_BAR(id) asm volatile("bar.sync %0, %1;" :: "r"(id), "r"(128) : "memory")

// ---------------- fused persistent kernel ----------------
__global__ void __launch_bounds__(256, 1)
fused_kernel(const float* __restrict__ X,
             const void* __restrict__ targets_raw,
             const float* __restrict__ LF,
             float* __restrict__ out) {
    __shared__ __align__(16) char arena[2 * STAGE_B];   // 40 KB, reused per phase
    __shared__ float ws[8];
    __shared__ float sapv[2][4], sanv[2][4];
    __shared__ int   sapj[2][4], sanj[2][4];
    __shared__ int   s_pi[2], s_ni[2];
    __shared__ float dA[2][PARTS][PARTS], dB[2][PARTS][PARTS];
    __shared__ float res[2][2];
    __shared__ int   s_last[2];
    __shared__ float wa[2][4], wb[2][4];

    const int b = blockIdx.x;
    const int t = threadIdx.x;

    // ================= phase 0: fp32 -> bf16 hi/lo split + row norms =========
#pragma unroll 1
    for (int k = 0; k < 4; k++) {
        const int row = b + GRID * k;
        if (row < N) {
            const float4* x4 = reinterpret_cast<const float4*>(X + (size_t)row * D);
            __nv_bfloat162* xh2 = reinterpret_cast<__nv_bfloat162*>(g_xh + (size_t)row * D);
            __nv_bfloat162* xl2 = reinterpret_cast<__nv_bfloat162*>(g_xl + (size_t)row * D);
            float s = 0.0f;
#pragma unroll
            for (int it = 0; it < 2; it++) {
                int idx = t + 256 * it;
                float4 v = x4[idx];
                s += v.x * v.x + v.y * v.y + v.z * v.z + v.w * v.w;
                __nv_bfloat16 hx = __float2bfloat16_rn(v.x);
                __nv_bfloat16 hy = __float2bfloat16_rn(v.y);
                __nv_bfloat16 hz = __float2bfloat16_rn(v.z);
                __nv_bfloat16 hw = __float2bfloat16_rn(v.w);
                __nv_bfloat16 lx = __float2bfloat16_rn(v.x - __bfloat162float(hx));
                __nv_bfloat16 ly = __float2bfloat16_rn(v.y - __bfloat162float(hy));
                __nv_bfloat16 lz = __float2bfloat16_rn(v.z - __bfloat162float(hz));
                __nv_bfloat16 lw = __float2bfloat16_rn(v.w - __bfloat162float(hw));
                xh2[idx * 2]     = __nv_bfloat162(hx, hy);
                xh2[idx * 2 + 1] = __nv_bfloat162(hz, hw);
                xl2[idx * 2]     = __nv_bfloat162(lx, ly);
                xl2[idx * 2 + 1] = __nv_bfloat162(lz, lw);
            }
#pragma unroll
            for (int o = 16; o > 0; o >>= 1) s += __shfl_down_sync(0xffffffffu, s, o);
            if ((t & 31) == 0) ws[t >> 5] = s;
            __syncthreads();
            if (t < 8) {
                s = ws[t];
#pragma unroll
                for (int o = 4; o > 0; o >>= 1) s += __shfl_down_sync(0xffu, s, o);
                if (t == 0) g_sq[row] = s;
            }
            __syncthreads();
        }
    }
    grid_bar(&g_bar0);

    // ================= phase 1: Gram (mma.sync bf16 3-term, R9 body) =========
    if (b < NTILES * SPLITK) {
        const unsigned smu = s2u(arena);
        const int wid  = t >> 5;
        const int lane = t & 31;
        const int wr   = wid & 3;
        const int wc   = wid >> 2;
        const int tile = b % NTILES;
        const int split = b / NTILES;
        const int m0   = (int)c_mt[tile] * 64;
        const int n0   = (int)c_nt[tile] * 64;
        const int kz   = split * KSPLIT;

        const int lr  = t >> 2;
        const int lch = t & 3;
        const unsigned dst_off = (unsigned)(lr * SM_STRIDE + lch * 16);
        const size_t   src_off = (size_t)lr * D + lch * 8;
        const __nv_bfloat16* Amh = g_xh + (size_t)m0 * D + src_off;
        const __nv_bfloat16* Aml = g_xl + (size_t)m0 * D + src_off;
        const __nv_bfloat16* Bnh = g_xh + (size_t)n0 * D + src_off;
        const __nv_bfloat16* Bnl = g_xl + (size_t)n0 * D + src_off;

        const unsigned aOff = (unsigned)((wr * 16 + (lane & 15)) * SM_STRIDE
                                         + ((lane >> 4) << 4));
        unsigned bOff[2];
#pragma unroll
        for (int p = 0; p < 2; p++)
            bOff[p] = (unsigned)((wc * 32 + p * 16 + ((lane >> 4) & 1) * 8 + (lane & 7))
                                 * SM_STRIDE + ((lane >> 3) & 1) * 16);

        float acc[4][4];
#pragma unroll
        for (int nt = 0; nt < 4; nt++)
#pragma unroll
            for (int e = 0; e < 4; e++) acc[nt][e] = 0.0f;

#pragma unroll
        for (int c = 0; c < 2; c++) {
            const unsigned sb = smu + c * STAGE_B + dst_off;
            const size_t   gk = kz + c * KC;
            cpa16(sb,              Amh + gk);
            cpa16(sb + TILE_B,     Aml + gk);
            cpa16(sb + 2 * TILE_B, Bnh + gk);
            cpa16(sb + 3 * TILE_B, Bnl + gk);
            asm volatile("cp.async.commit_group;" ::: "memory");
        }

#pragma unroll 1
        for (int c = 0; c < NCH; c++) {
            if (c < NCH - 1) asm volatile("cp.async.wait_group 1;" ::: "memory");
            else             asm volatile("cp.async.wait_group 0;" ::: "memory");
            __syncthreads();

            const unsigned st = smu + (c & 1) * STAGE_B;
#pragma unroll
            for (int s16 = 0; s16 < 2; s16++) {
                unsigned ah[4], al[4], bh[8], bl[8];
                const unsigned ka = st + aOff + s16 * 32;
                ldm4(ah, ka);
                ldm4(al, ka + TILE_B);
#pragma unroll
                for (int p = 0; p < 2; p++) {
                    const unsigned kb = st + bOff[p] + s16 * 32;
                    ldm4(&bh[p * 4], kb + 2 * TILE_B);
                    ldm4(&bl[p * 4], kb + 3 * TILE_B);
                }
#pragma unroll
                for (int nt = 0; nt < 4; nt++) {
                    const int bi = (nt >> 1) * 4 + (nt & 1) * 2;
                    mma_bf16(acc[nt], ah, bh[bi], bh[bi + 1]);
                    mma_bf16(acc[nt], ah, bl[bi], bl[bi + 1]);
                    mma_bf16(acc[nt], al, bh[bi], bh[bi + 1]);
                }
            }
            __syncthreads();

            if (c + 2 < NCH) {
                const unsigned sb = smu + (c & 1) * STAGE_B + dst_off;
                const size_t   gk = kz + (size_t)(c + 2) * KC;
                cpa16(sb,              Amh + gk);
                cpa16(sb + TILE_B,     Aml + gk);
                cpa16(sb + 2 * TILE_B, Bnh + gk);
                cpa16(sb + 3 * TILE_B, Bnl + gk);
                asm volatile("cp.async.commit_group;" ::: "memory");
            }
        }

        float* outg = g_gram[split];
        const int rbase = m0 + wr * 16 + (lane >> 2);
        const bool mirror = (m0 != n0);
#pragma unroll
        for (int nt = 0; nt < 4; nt++) {
            const int col = n0 + wc * 32 + nt * 8 + (lane & 3) * 2;
            *reinterpret_cast<float2*>(&outg[(size_t)rbase * N + col]) =
                make_float2(acc[nt][0], acc[nt][1]);
            *reinterpret_cast<float2*>(&outg[(size_t)(rbase + 8) * N + col]) =
                make_float2(acc[nt][2], acc[nt][3]);
            if (mirror) {
                outg[(size_t)col * N + rbase]           = acc[nt][0];
                outg[(size_t)(col + 1) * N + rbase]     = acc[nt][1];
                outg[(size_t)col * N + rbase + 8]       = acc[nt][2];
                outg[(size_t)(col + 1) * N + rbase + 8] = acc[nt][3];
            }
        }
    }
    grid_bar(&g_bar1);

    // ================= phase 2: mining + DTW, 2 groups of 128 threads ========
    const int g    = t >> 7;            // group 0/1
    const int tl   = t & 127;           // thread-in-group
    const int barid = 1 + g;            // named barriers 1 and 2
    float* saG = reinterpret_cast<float*>(arena + g * GRP_B);
    float* sbG = saG + PARTS * LSTRIDE;
    float* scG = sbG + PARTS * LSTRIDE;

    const int* ip = reinterpret_cast<const int*>(targets_raw);
    const int stride = (ip[5] == 0) ? 2 : 1;   // int64 vs int32 targets

#pragma unroll 1
    for (int r = 0; r < 2; r++) {
        const int i = b + GRID * (g + 2 * r);
        if (i < N) {
            const int   ti  = ip[(size_t)i * stride];
            const float sqi = g_sq[i];

            // ---- mining: 4 consecutive j per thread ----
            const int j0 = tl * 4;
            float4 gs = make_float4(0.f, 0.f, 0.f, 0.f);
#pragma unroll
            for (int s = 0; s < SPLITK; s++) {
                float4 v = *reinterpret_cast<const float4*>(
                    &g_gram[s][(size_t)i * N + j0]);
                gs.x += v.x; gs.y += v.y; gs.z += v.z; gs.w += v.w;
            }
            float apv = -3.0e38f; int apj = N;
            float anv =  3.0e38f; int anj = N;
            float gv[4] = {gs.x, gs.y, gs.z, gs.w};
#pragma unroll
            for (int u = 0; u < 4; u++) {
                int j = j0 + u;
                float d = sqrtf(fmaxf(sqi + g_sq[j] - 2.0f * gv[u], 1e-12f));
                if (ip[(size_t)j * stride] == ti) {
                    if (d > apv) { apv = d; apj = j; }   // strict > keeps first idx
                } else {
                    if (d < anv) { anv = d; anj = j; }
                }
            }
#pragma unroll
            for (int o = 16; o > 0; o >>= 1) {
                float v = __shfl_down_sync(0xffffffffu, apv, o);
                int   j = __shfl_down_sync(0xffffffffu, apj, o);
                if (v > apv || (v == apv && j < apj)) { apv = v; apj = j; }
                v = __shfl_down_sync(0xffffffffu, anv, o);
                j = __shfl_down_sync(0xffffffffu, anj, o);
                if (v < anv || (v == anv && j < anj)) { anv = v; anj = j; }
            }
            if ((tl & 31) == 0) {
                int w = tl >> 5;
                sapv[g][w] = apv; sapj[g][w] = apj;
                sanv[g][w] = anv; sanj[g][w] = anj;
            }
            GROUP_BAR(barid);
            if (tl == 0) {
                for (int w = 1; w < 4; w++) {
                    if (sapv[g][w] > apv || (sapv[g][w] == apv && sapj[g][w] < apj)) {
                        apv = sapv[g][w]; apj = sapj[g][w];
                    }
                    if (sanv[g][w] < anv || (sanv[g][w] == anv && sanj[g][w] < anj)) {
                        anv = sanv[g][w]; anj = sanj[g][w];
                    }
                }
                s_pi[g] = apj;
                s_ni[g] = anj;
                g_gl[i] = fmaxf(0.0f, MARGIN + apv - anv);
            }
            GROUP_BAR(barid);

            // ---- stage LF rows [d][p] -> part-major sa[p][d] ----
            const float* A = LF + (size_t)i        * (LDIM * PARTS);
            const float* B = LF + (size_t)s_pi[g]  * (LDIM * PARTS);
            const float* C = LF + (size_t)s_ni[g]  * (LDIM * PARTS);
            for (int idx = tl; idx < LDIM * PARTS; idx += 128) {
                int d = idx >> 3, p = idx & 7;
                saG[p * LSTRIDE + d] = A[idx];
                sbG[p * LSTRIDE + d] = B[idx];
                scG[p * LSTRIDE + d] = C[idx];
            }
            GROUP_BAR(barid);

            // ---- 8x8 part-distance matrices (64 active threads) ----
            if (tl < 64) {
                const int p = tl >> 3, q = tl & 7;
                float s1 = 0.0f, s2 = 0.0f;
#pragma unroll 8
                for (int d = 0; d < LDIM; d++) {
                    float av = saG[p * LSTRIDE + d];
                    float x = av - sbG[q * LSTRIDE + d]; s1 += x * x;
                    float y = av - scG[q * LSTRIDE + d]; s2 += y * y;
                }
                dA[g][p][q] = tanhf(0.5f * sqrtf(fmaxf(s1, 1e-12f)));
                dB[g][p][q] = tanhf(0.5f * sqrtf(fmaxf(s2, 1e-12f)));
            }
            GROUP_BAR(barid);

            // ---- DTW shortest path (2 active threads) ----
            if (tl < 2) {
                float (*dm)[PARTS] = (tl == 0) ? dA[g] : dB[g];
                float prev[PARTS];
                prev[0] = 0.0f;
#pragma unroll
                for (int j = 1; j < PARTS; j++) prev[j] = 1e9f;
#pragma unroll
                for (int rr = 0; rr < PARTS; rr++) {
                    float left = 1e9f;
#pragma unroll
                    for (int j = 0; j < PARTS; j++) {
                        float cur = dm[rr][j] + fminf(prev[j], left);
                        prev[j] = cur;
                        left = cur;
                    }
                }
                res[g][tl] = prev[PARTS - 1];
            }
            GROUP_BAR(barid);

            // ---- item completion + possible final reduction ----
            if (tl == 0) {
                g_ll[i] = fmaxf(0.0f, MARGIN + res[g][0] - res[g][1]);
                __threadfence();
                int old = atomicAdd(&g_cnt, 1);
                s_last[g] = (old == N - 1) ? 1 : 0;
            }
            GROUP_BAR(barid);
            if (s_last[g]) {
                float a = 0.0f, bb = 0.0f;
#pragma unroll
                for (int j = tl; j < N; j += 128) {
                    a  += __ldcg(&g_gl[j]);
                    bb += __ldcg(&g_ll[j]);
                }
#pragma unroll
                for (int o = 16; o > 0; o >>= 1) {
                    a  += __shfl_down_sync(0xffffffffu, a, o);
                    bb += __shfl_down_sync(0xffffffffu, bb, o);
                }
                if ((tl & 31) == 0) { wa[g][tl >> 5] = a; wb[g][tl >> 5] = bb; }
                GROUP_BAR(barid);
                if (tl == 0) {
                    a  = wa[g][0] + wa[g][1] + wa[g][2] + wa[g][3];
                    bb = wb[g][0] + wb[g][1] + wb[g][2] + wb[g][3];
                    out[0] = a  * (1.0f / N);
                    out[1] = bb * (1.0f / N);
                    g_cnt  = 0;          // reset for next graph replay
                    g_bar0 = 0;
                    g_bar1 = 0;
                }
            }
        }
    }
}

// ---------------- launch ----------------
extern "C" void kernel_launch(void* const* d_in, const int* in_sizes, int n_in,
                              void* d_out, int out_size) {
    const float* X  = (const float*)d_in[0];
    const void*  TG = d_in[1];
    const float* LF = (const float*)d_in[2];
    float* out = (float*)d_out;

    fused_kernel<<<GRID, 256>>>(X, TG, LF, out);
}

// round 17
// speedup vs baseline: 1.1032x; 1.1032x over previous
#include <cuda_runtime.h>
#include <cuda_bf16.h>

#define N       512
#define D       2048
#define LDIM    128
#define PARTS   8
#define SPLITK  4
#define KSPLIT  (D / SPLITK)       // 512
#define KC      32                 // k per pipeline chunk
#define NCH     (KSPLIT / KC)      // 16
#define NTILES  36
#define NGRAM   (NTILES * SPLITK)  // 144 gram CTAs
#define GRID    296                // 2 CTAs per SM, all co-resident
#define MARGIN  0.3f

#define SM_STRIDE 80                       // bytes per smem row (32 bf16 + 8 pad)
#define TILE_B    (64 * SM_STRIDE)         // 5120
#define STAGE_B   (4 * TILE_B)             // 20480 (Ah, Al, Bh, Bl)
#define LSTRIDE   (LDIM + 4)               // floats per part row
#define GRP_B     16384                    // arena bytes per mine group
#define LF_BYTES  (N * LDIM * PARTS * 4)   // 2 MB

// ---------------- device scratch (static allocation only) ----------------
__device__ float          g_sq[N];
__device__ __nv_bfloat16  g_xh[N * D];
__device__ __nv_bfloat16  g_xl[N * D];
__device__ float          g_gram[SPLITK][N * N];
__device__ float          g_gl[N];
__device__ float          g_ll[N];
__device__ int            g_bar0 = 0;
__device__ int            g_bar1 = 0;
__device__ int            g_cnt  = 0;

// symmetric tile list: all (mt, nt) with mt <= nt on the 8x8 grid of 64x64 tiles
__constant__ unsigned char c_mt[NTILES] = {
    0,0,0,0,0,0,0,0, 1,1,1,1,1,1,1, 2,2,2,2,2,2, 3,3,3,3,3, 4,4,4,4, 5,5,5, 6,6, 7};
__constant__ unsigned char c_nt[NTILES] = {
    0,1,2,3,4,5,6,7, 1,2,3,4,5,6,7, 2,3,4,5,6,7, 3,4,5,6,7, 4,5,6,7, 5,6,7, 6,7, 7};

// ---------------- helpers ----------------
__device__ __forceinline__ unsigned s2u(const void* p) {
    unsigned a;
    asm("{ .reg .u64 t; cvta.to.shared.u64 t, %1; cvt.u32.u64 %0, t; }"
        : "=r"(a) : "l"(p));
    return a;
}
__device__ __forceinline__ void cpa16(unsigned saddr, const void* gaddr) {
    asm volatile("cp.async.cg.shared.global [%0], [%1], 16;"
                 :: "r"(saddr), "l"(gaddr) : "memory");
}
__device__ __forceinline__ void ldm4(unsigned* f, unsigned saddr) {
    asm volatile("ldmatrix.sync.aligned.m8n8.x4.shared.b16 {%0,%1,%2,%3}, [%4];"
                 : "=r"(f[0]), "=r"(f[1]), "=r"(f[2]), "=r"(f[3]) : "r"(saddr));
}
__device__ __forceinline__ void mma_bf16(float* d, const unsigned* a,
                                         unsigned b0, unsigned b1) {
    asm volatile(
        "mma.sync.aligned.m16n8k16.row.col.f32.bf16.bf16.f32 "
        "{%0,%1,%2,%3}, {%4,%5,%6,%7}, {%8,%9}, {%0,%1,%2,%3};"
        : "+f"(d[0]), "+f"(d[1]), "+f"(d[2]), "+f"(d[3])
        : "r"(a[0]), "r"(a[1]), "r"(a[2]), "r"(a[3]), "r"(b0), "r"(b1));
}
__device__ __forceinline__ int ld_acq(const int* p) {
    int v;
    asm volatile("ld.acquire.gpu.global.b32 %0, [%1];" : "=r"(v) : "l"(p) : "memory");
    return v;
}
// grid-wide barrier: all GRID CTAs are co-resident (2 per SM, wave 1).
__device__ __forceinline__ void grid_bar(int* ctr) {
    __threadfence();
    __syncthreads();
    if (threadIdx.x == 0) {
        atomicAdd(ctr, 1);
        while (ld_acq(ctr) < GRID) { }
    }
    __syncthreads();
}
#define GROUP_BAR(id) asm volatile("bar.sync %0, %1;" :: "r"(id), "r"(128) : "memory")

// ---------------- fused persistent kernel ----------------
__global__ void __launch_bounds__(256, 2)
fused_kernel(const float* __restrict__ X,
             const void* __restrict__ targets_raw,
             const float* __restrict__ LF,
             float* __restrict__ out) {
    __shared__ __align__(16) char arena[2 * STAGE_B];   // 40 KB, reused per phase
    __shared__ float ws[8];
    __shared__ float sapv[2][4], sanv[2][4];
    __shared__ int   sapj[2][4], sanj[2][4];
    __shared__ int   s_pi[2], s_ni[2];
    __shared__ float dA[2][PARTS][PARTS], dB[2][PARTS][PARTS];
    __shared__ float res[2][2];
    __shared__ int   s_last[2];
    __shared__ float wa[2][4], wb[2][4];

    const int b = blockIdx.x;
    const int t = threadIdx.x;

    // ================= phase 0: fp32 -> bf16 hi/lo split + row norms =========
#pragma unroll 1
    for (int k = 0; k < 2; k++) {
        const int row = b + GRID * k;
        if (row < N) {
            const float4* x4 = reinterpret_cast<const float4*>(X + (size_t)row * D);
            __nv_bfloat162* xh2 = reinterpret_cast<__nv_bfloat162*>(g_xh + (size_t)row * D);
            __nv_bfloat162* xl2 = reinterpret_cast<__nv_bfloat162*>(g_xl + (size_t)row * D);
            float s = 0.0f;
#pragma unroll
            for (int it = 0; it < 2; it++) {
                int idx = t + 256 * it;
                float4 v = x4[idx];
                s += v.x * v.x + v.y * v.y + v.z * v.z + v.w * v.w;
                __nv_bfloat16 hx = __float2bfloat16_rn(v.x);
                __nv_bfloat16 hy = __float2bfloat16_rn(v.y);
                __nv_bfloat16 hz = __float2bfloat16_rn(v.z);
                __nv_bfloat16 hw = __float2bfloat16_rn(v.w);
                __nv_bfloat16 lx = __float2bfloat16_rn(v.x - __bfloat162float(hx));
                __nv_bfloat16 ly = __float2bfloat16_rn(v.y - __bfloat162float(hy));
                __nv_bfloat16 lz = __float2bfloat16_rn(v.z - __bfloat162float(hz));
                __nv_bfloat16 lw = __float2bfloat16_rn(v.w - __bfloat162float(hw));
                xh2[idx * 2]     = __nv_bfloat162(hx, hy);
                xh2[idx * 2 + 1] = __nv_bfloat162(hz, hw);
                xl2[idx * 2]     = __nv_bfloat162(lx, ly);
                xl2[idx * 2 + 1] = __nv_bfloat162(lz, lw);
            }
#pragma unroll
            for (int o = 16; o > 0; o >>= 1) s += __shfl_down_sync(0xffffffffu, s, o);
            if ((t & 31) == 0) ws[t >> 5] = s;
            __syncthreads();
            if (t < 8) {
                s = ws[t];
#pragma unroll
                for (int o = 4; o > 0; o >>= 1) s += __shfl_down_sync(0xffu, s, o);
                if (t == 0) g_sq[row] = s;
            }
            __syncthreads();
        }
    }
    grid_bar(&g_bar0);

    // ================= phase 1: Gram (144 CTAs) / LF L2-prefetch (152 CTAs) ==
    if (b < NGRAM) {
        const unsigned smu = s2u(arena);
        const int wid  = t >> 5;
        const int lane = t & 31;
        const int wr   = wid & 3;
        const int wc   = wid >> 2;
        const int tile = b % NTILES;
        const int split = b / NTILES;
        const int m0   = (int)c_mt[tile] * 64;
        const int n0   = (int)c_nt[tile] * 64;
        const int kz   = split * KSPLIT;

        const int lr  = t >> 2;
        const int lch = t & 3;
        const unsigned dst_off = (unsigned)(lr * SM_STRIDE + lch * 16);
        const size_t   src_off = (size_t)lr * D + lch * 8;
        const __nv_bfloat16* Amh = g_xh + (size_t)m0 * D + src_off;
        const __nv_bfloat16* Aml = g_xl + (size_t)m0 * D + src_off;
        const __nv_bfloat16* Bnh = g_xh + (size_t)n0 * D + src_off;
        const __nv_bfloat16* Bnl = g_xl + (size_t)n0 * D + src_off;

        const unsigned aOff = (unsigned)((wr * 16 + (lane & 15)) * SM_STRIDE
                                         + ((lane >> 4) << 4));
        unsigned bOff[2];
#pragma unroll
        for (int p = 0; p < 2; p++)
            bOff[p] = (unsigned)((wc * 32 + p * 16 + ((lane >> 4) & 1) * 8 + (lane & 7))
                                 * SM_STRIDE + ((lane >> 3) & 1) * 16);

        float acc[4][4];
#pragma unroll
        for (int nt = 0; nt < 4; nt++)
#pragma unroll
            for (int e = 0; e < 4; e++) acc[nt][e] = 0.0f;

#pragma unroll
        for (int c = 0; c < 2; c++) {
            const unsigned sb = smu + c * STAGE_B + dst_off;
            const size_t   gk = kz + c * KC;
            cpa16(sb,              Amh + gk);
            cpa16(sb + TILE_B,     Aml + gk);
            cpa16(sb + 2 * TILE_B, Bnh + gk);
            cpa16(sb + 3 * TILE_B, Bnl + gk);
            asm volatile("cp.async.commit_group;" ::: "memory");
        }

#pragma unroll 1
        for (int c = 0; c < NCH; c++) {
            if (c < NCH - 1) asm volatile("cp.async.wait_group 1;" ::: "memory");
            else             asm volatile("cp.async.wait_group 0;" ::: "memory");
            __syncthreads();

            const unsigned st = smu + (c & 1) * STAGE_B;
#pragma unroll
            for (int s16 = 0; s16 < 2; s16++) {
                unsigned ah[4], al[4], bh[8], bl[8];
                const unsigned ka = st + aOff + s16 * 32;
                ldm4(ah, ka);
                ldm4(al, ka + TILE_B);
#pragma unroll
                for (int p = 0; p < 2; p++) {
                    const unsigned kb = st + bOff[p] + s16 * 32;
                    ldm4(&bh[p * 4], kb + 2 * TILE_B);
                    ldm4(&bl[p * 4], kb + 3 * TILE_B);
                }
#pragma unroll
                for (int nt = 0; nt < 4; nt++) {
                    const int bi = (nt >> 1) * 4 + (nt & 1) * 2;
                    mma_bf16(acc[nt], ah, bh[bi], bh[bi + 1]);
                    mma_bf16(acc[nt], ah, bl[bi], bl[bi + 1]);
                    mma_bf16(acc[nt], al, bh[bi], bh[bi + 1]);
                }
            }
            __syncthreads();

            if (c + 2 < NCH) {
                const unsigned sb = smu + (c & 1) * STAGE_B + dst_off;
                const size_t   gk = kz + (size_t)(c + 2) * KC;
                cpa16(sb,              Amh + gk);
                cpa16(sb + TILE_B,     Aml + gk);
                cpa16(sb + 2 * TILE_B, Bnh + gk);
                cpa16(sb + 3 * TILE_B, Bnl + gk);
                asm volatile("cp.async.commit_group;" ::: "memory");
            }
        }

        float* outg = g_gram[split];
        const int rbase = m0 + wr * 16 + (lane >> 2);
        const bool mirror = (m0 != n0);
#pragma unroll
        for (int nt = 0; nt < 4; nt++) {
            const int col = n0 + wc * 32 + nt * 8 + (lane & 3) * 2;
            *reinterpret_cast<float2*>(&outg[(size_t)rbase * N + col]) =
                make_float2(acc[nt][0], acc[nt][1]);
            *reinterpret_cast<float2*>(&outg[(size_t)(rbase + 8) * N + col]) =
                make_float2(acc[nt][2], acc[nt][3]);
            if (mirror) {
                outg[(size_t)col * N + rbase]           = acc[nt][0];
                outg[(size_t)(col + 1) * N + rbase]     = acc[nt][1];
                outg[(size_t)col * N + rbase + 8]       = acc[nt][2];
                outg[(size_t)(col + 1) * N + rbase + 8] = acc[nt][3];
            }
        }
    } else {
        // partner CTAs: warm L2 with the whole LF array for phase 2
        const char* lf = reinterpret_cast<const char*>(LF);
        const int pb = b - NGRAM;                 // 0..151
        for (size_t off = (size_t)(pb * 256 + t) * 128;
             off < (size_t)LF_BYTES;
             off += (size_t)(GRID - NGRAM) * 256 * 128)
            asm volatile("prefetch.global.L2 [%0];" :: "l"(lf + off));
    }
    grid_bar(&g_bar1);

    // ================= phase 2: mining + DTW, 2 groups of 128, ONE round =====
    const int g    = t >> 7;            // group 0/1
    const int tl   = t & 127;           // thread-in-group
    const int barid = 1 + g;            // named barriers 1 and 2
    float* saG = reinterpret_cast<float*>(arena + g * GRP_B);
    float* sbG = saG + PARTS * LSTRIDE;
    float* scG = sbG + PARTS * LSTRIDE;

    const int* ip = reinterpret_cast<const int*>(targets_raw);
    const int stride = (ip[5] == 0) ? 2 : 1;   // int64 vs int32 targets

    const int i = b + GRID * g;          // 0..591, valid if < N
    if (i < N) {
        const int   ti  = ip[(size_t)i * stride];
        const float sqi = g_sq[i];

        // ---- mining: 4 consecutive j per thread ----
        const int j0 = tl * 4;
        float4 gs = make_float4(0.f, 0.f, 0.f, 0.f);
#pragma unroll
        for (int s = 0; s < SPLITK; s++) {
            float4 v = *reinterpret_cast<const float4*>(
                &g_gram[s][(size_t)i * N + j0]);
            gs.x += v.x; gs.y += v.y; gs.z += v.z; gs.w += v.w;
        }
        float apv = -3.0e38f; int apj = N;
        float anv =  3.0e38f; int anj = N;
        float gv[4] = {gs.x, gs.y, gs.z, gs.w};
#pragma unroll
        for (int u = 0; u < 4; u++) {
            int j = j0 + u;
            float d = sqrtf(fmaxf(sqi + g_sq[j] - 2.0f * gv[u], 1e-12f));
            if (ip[(size_t)j * stride] == ti) {
                if (d > apv) { apv = d; apj = j; }   // strict > keeps first idx
            } else {
                if (d < anv) { anv = d; anj = j; }
            }
        }
#pragma unroll
        for (int o = 16; o > 0; o >>= 1) {
            float v = __shfl_down_sync(0xffffffffu, apv, o);
            int   j = __shfl_down_sync(0xffffffffu, apj, o);
            if (v > apv || (v == apv && j < apj)) { apv = v; apj = j; }
            v = __shfl_down_sync(0xffffffffu, anv, o);
            j = __shfl_down_sync(0xffffffffu, anj, o);
            if (v < anv || (v == anv && j < anj)) { anv = v; anj = j; }
        }
        if ((tl & 31) == 0) {
            int w = tl >> 5;
            sapv[g][w] = apv; sapj[g][w] = apj;
            sanv[g][w] = anv; sanj[g][w] = anj;
        }
        GROUP_BAR(barid);
        if (tl == 0) {
            for (int w = 1; w < 4; w++) {
                if (sapv[g][w] > apv || (sapv[g][w] == apv && sapj[g][w] < apj)) {
                    apv = sapv[g][w]; apj = sapj[g][w];
                }
                if (sanv[g][w] < anv || (sanv[g][w] == anv && sanj[g][w] < anj)) {
                    anv = sanv[g][w]; anj = sanj[g][w];
                }
            }
            s_pi[g] = apj;
            s_ni[g] = anj;
            g_gl[i] = fmaxf(0.0f, MARGIN + apv - anv);
        }
        GROUP_BAR(barid);

        // ---- stage LF rows [d][p] -> part-major sa[p][d] ----
        const float* A = LF + (size_t)i        * (LDIM * PARTS);
        const float* B = LF + (size_t)s_pi[g]  * (LDIM * PARTS);
        const float* C = LF + (size_t)s_ni[g]  * (LDIM * PARTS);
        for (int idx = tl; idx < LDIM * PARTS; idx += 128) {
            int d = idx >> 3, p = idx & 7;
            saG[p * LSTRIDE + d] = A[idx];
            sbG[p * LSTRIDE + d] = B[idx];
            scG[p * LSTRIDE + d] = C[idx];
        }
        GROUP_BAR(barid);

        // ---- 8x8 part-distance matrices (64 active threads) ----
        if (tl < 64) {
            const int p = tl >> 3, q = tl & 7;
            float s1 = 0.0f, s2 = 0.0f;
#pragma unroll 8
            for (int d = 0; d < LDIM; d++) {
                float av = saG[p * LSTRIDE + d];
                float x = av - sbG[q * LSTRIDE + d]; s1 += x * x;
                float y = av - scG[q * LSTRIDE + d]; s2 += y * y;
            }
            dA[g][p][q] = tanhf(0.5f * sqrtf(fmaxf(s1, 1e-12f)));
            dB[g][p][q] = tanhf(0.5f * sqrtf(fmaxf(s2, 1e-12f)));
        }
        GROUP_BAR(barid);

        // ---- DTW shortest path (2 active threads) ----
        if (tl < 2) {
            float (*dm)[PARTS] = (tl == 0) ? dA[g] : dB[g];
            float prev[PARTS];
            prev[0] = 0.0f;
#pragma unroll
            for (int j = 1; j < PARTS; j++) prev[j] = 1e9f;
#pragma unroll
            for (int rr = 0; rr < PARTS; rr++) {
                float left = 1e9f;
#pragma unroll
                for (int j = 0; j < PARTS; j++) {
                    float cur = dm[rr][j] + fminf(prev[j], left);
                    prev[j] = cur;
                    left = cur;
                }
            }
            res[g][tl] = prev[PARTS - 1];
        }
        GROUP_BAR(barid);

        // ---- item completion + possible final reduction ----
        if (tl == 0) {
            g_ll[i] = fmaxf(0.0f, MARGIN + res[g][0] - res[g][1]);
            __threadfence();
            int old = atomicAdd(&g_cnt, 1);
            s_last[g] = (old == N - 1) ? 1 : 0;
        }
        GROUP_BAR(barid);
        if (s_last[g]) {
            float a = 0.0f, bb = 0.0f;
#pragma unroll
            for (int j = tl; j < N; j += 128) {
                a  += __ldcg(&g_gl[j]);
                bb += __ldcg(&g_ll[j]);
            }
#pragma unroll
            for (int o = 16; o > 0; o >>= 1) {
                a  += __shfl_down_sync(0xffffffffu, a, o);
                bb += __shfl_down_sync(0xffffffffu, bb, o);
            }
            if ((tl & 31) == 0) { wa[g][tl >> 5] = a; wb[g][tl >> 5] = bb; }
            GROUP_BAR(barid);
            if (tl == 0) {
                a  = wa[g][0] + wa[g][1] + wa[g][2] + wa[g][3];
                bb = wb[g][0] + wb[g][1] + wb[g][2] + wb[g][3];
                out[0] = a  * (1.0f / N);
                out[1] = bb * (1.0f / N);
                g_cnt  = 0;          // reset for next graph replay
                g_bar0 = 0;
                g_bar1 = 0;
            }
        }
    }
}

// ---------------- launch ----------------
extern "C" void kernel_launch(void* const* d_in, const int* in_sizes, int n_in,
                              void* d_out, int out_size) {
    const float* X  = (const float*)d_in[0];
    const void*  TG = d_in[1];
    const float* LF = (const float*)d_in[2];
    float* out = (float*)d_out;

    fused_kernel<<<GRID, 256>>>(X, TG, LF, out);
}